// round 11
// baseline (speedup 1.0000x reference)
#include <cuda_runtime.h>
#include <cuda_bf16.h>

// InternalCoordinateTransform.
// z_mat row r = (r+3, r+2, r+1, r) => row r reads atoms r..r+3 (floats
// 3r..3r+11), writes floats 3r+9..3r+11. Thread g handles rows 4g+1..4g+4:
// atoms 4g..4g+7 = 6 aligned LDS.128, results = 3 aligned STG.128.
// Params pre-packed (prep kernel) into group-SoA float4s: 6 LDG.128/group.
// Per-row math kept INDEPENDENT (R8/R10 lesson: rolling-window dependency
// chain kills ILP and issue%). 320 threads: 624/320 -> max 2 iters vs avg
// 1.95 (97.5% balance) and 60 theoretical warps/SM.
// Lessons: R4 no reg cap; R5 no per-row scalar LDG; R7 no shuffle.

#define NDIM    7500
#define NF4     1875          // NDIM/4
#define NGROUPS 624           // rows 1..2496 in groups of 4; row 0 special
#define TPB     320
#define PI_F    3.14159265358979f
#define TWO_PI  6.28318530717959f

// Group-SoA packed params, k=0..5: {isb}, {-mb*isb}, {isa}, {-ma*isa}, {md}, {isd}
__device__ float4 g_prm[6 * NGROUPS];

__device__ __forceinline__ float rsqrt_ap(float x) {
    float r; asm("rsqrt.approx.f32 %0, %1;" : "=f"(r) : "f"(x)); return r;
}
__device__ __forceinline__ float sqrt_ap(float x) {
    float r; asm("sqrt.approx.f32 %0, %1;" : "=f"(r) : "f"(x)); return r;
}
__device__ __forceinline__ float rcp_ap(float x) {
    float r; asm("rcp.approx.f32 %0, %1;" : "=f"(r) : "f"(x)); return r;
}

// Hastings-style acos, |err| ~1e-7 rad, x in [-1,1].
__device__ __forceinline__ float acos_fast(float x) {
    float xa = fabsf(x);
    float p = -0.0012624911f;
    p = fmaf(p, xa,  0.0066700901f);
    p = fmaf(p, xa, -0.0170881256f);
    p = fmaf(p, xa,  0.0308918810f);
    p = fmaf(p, xa, -0.0501743046f);
    p = fmaf(p, xa,  0.0889789874f);
    p = fmaf(p, xa, -0.2145988016f);
    p = fmaf(p, xa,  1.5707963050f);
    float r = sqrt_ap(1.0f - xa) * p;
    return (x >= 0.0f) ? r : (PI_F - r);
}

// Full-quadrant atan2, |err| ~ few e-6 rad.
__device__ __forceinline__ float atan2_fast(float y, float x) {
    float ax = fabsf(x), ay = fabsf(y);
    float mx = fmaxf(fmaxf(ax, ay), 1e-35f);
    float mn = fminf(ax, ay);
    float t  = mn * rcp_ap(mx);
    float s  = t * t;
    float p = -0.01172120f;
    p = fmaf(p, s,  0.05265332f);
    p = fmaf(p, s, -0.11643287f);
    p = fmaf(p, s,  0.19354346f);
    p = fmaf(p, s, -0.33262347f);
    p = fmaf(p, s,  0.99997726f);
    float r = t * p;
    if (ay > ax)   r = 1.57079632679f - r;
    if (x < 0.0f)  r = PI_F - r;
    return copysignf(r, y);
}

// One z-row from 12 consecutive floats:
// p3=a[0..2], p2=a[3..5], p1=a[6..8], p4=a[9..11]
__device__ __forceinline__ void ic_row(const float* a, float& bond, float& ang, float& dihe)
{
    float d21x = a[3]-a[6], d21y = a[4]-a[7], d21z = a[5]-a[8];
    float d41x = a[9]-a[6], d41y = a[10]-a[7], d41z = a[11]-a[8];
    float s21 = fmaf(d21x,d21x, fmaf(d21y,d21y, d21z*d21z));
    float s41 = fmaf(d41x,d41x, fmaf(d41y,d41y, d41z*d41z));
    float r21 = rsqrt_ap(s21), r41 = rsqrt_ap(s41);
    bond = s41 * r41;
    float dotc = fmaf(d21x,d41x, fmaf(d21y,d41y, d21z*d41z));
    float cosang = fminf(fmaxf(dotc*r21*r41, -1.0f), 1.0f);
    ang = acos_fast(cosang);
    float ux = d21x*r21, uy = d21y*r21, uz = d21z*r21;
    float b0x = a[0]-a[3], b0y = a[1]-a[4], b0z = a[2]-a[5];
    float db0 = fmaf(b0x,ux, fmaf(b0y,uy, b0z*uz));
    float vx = fmaf(-db0,ux,b0x), vy = fmaf(-db0,uy,b0y), vz = fmaf(-db0,uz,b0z);
    float db2 = fmaf(d41x,ux, fmaf(d41y,uy, d41z*uz));
    float wx = fmaf(-db2,ux,d41x), wy = fmaf(-db2,uy,d41y), wz = fmaf(-db2,uz,d41z);
    float xx = fmaf(vx,wx, fmaf(vy,wy, vz*wz));
    float cx = fmaf(uy,vz,-uz*vy), cy = fmaf(uz,vx,-ux*vz), cz = fmaf(ux,vy,-uy*vx);
    float yy = fmaf(cx,wx, fmaf(cy,wy, cz*wz));
    dihe = atan2_fast(yy, xx);
}

__global__ void prep_kernel(const float* __restrict__ mb, const float* __restrict__ sb,
                            const float* __restrict__ ma, const float* __restrict__ sa,
                            const float* __restrict__ md, const float* __restrict__ sd)
{
    int g = blockIdx.x * blockDim.x + threadIdx.x;
    if (g >= NGROUPS) return;
    float4 v0, v1, v2, v3, v4, v5;
    float* p0 = (float*)&v0; float* p1 = (float*)&v1; float* p2 = (float*)&v2;
    float* p3 = (float*)&v3; float* p4 = (float*)&v4; float* p5 = (float*)&v5;
#pragma unroll
    for (int j = 0; j < 4; j++) {
        int r = 4 * g + 1 + j;
        float isb = rcp_ap(sb[r]);
        float isa = rcp_ap(sa[r]);
        float isd = rcp_ap(sd[r]);
        p0[j] = isb;   p1[j] = -mb[r] * isb;
        p2[j] = isa;   p3[j] = -ma[r] * isa;
        p4[j] = md[r]; p5[j] = isd;
    }
    g_prm[0 * NGROUPS + g] = v0;
    g_prm[1 * NGROUPS + g] = v1;
    g_prm[2 * NGROUPS + g] = v2;
    g_prm[3 * NGROUPS + g] = v3;
    g_prm[4 * NGROUPS + g] = v4;
    g_prm[5 * NGROUPS + g] = v5;
}

__global__ __launch_bounds__(TPB)
void ict_kernel(const float* __restrict__ x,
                const float* __restrict__ mb, const float* __restrict__ sb,
                const float* __restrict__ ma, const float* __restrict__ sa,
                const float* __restrict__ md, const float* __restrict__ sd,
                float* __restrict__ out)
{
    __shared__ float4 A4[NF4];                 // the batch row, 30KB
    const int b   = blockIdx.x;
    const int tid = threadIdx.x;
    const size_t base = (size_t)b * NDIM;
    const float* A = (const float*)A4;
    float4* __restrict__ outv = (float4*)(out + base);

    // Stage row (coalesced float4): 1875 / 320 -> 6 strided iterations.
    const float4* __restrict__ xin = (const float4*)(x + base);
#pragma unroll
    for (int k = 0; k < 6; k++) {
        int idx = tid + k * TPB;
        if (idx < NF4) A4[idx] = xin[idx];
    }
    __syncthreads();

    for (int g = tid; g < NGROUPS; g += TPB) {
        // ---- atoms 4g..4g+7 = floats 12g..12g+23: 6 aligned LDS.128 ----
        float a[24];
#pragma unroll
        for (int q = 0; q < 6; q++) {
            float4 f = A4[3 * g + q];
            a[4*q] = f.x; a[4*q+1] = f.y; a[4*q+2] = f.z; a[4*q+3] = f.w;
        }

        // ---- packed params (6 aligned LDG.128, L2-resident) ----
        float4 c0 = g_prm[0 * NGROUPS + g];
        float4 c1 = g_prm[1 * NGROUPS + g];
        float4 c2 = g_prm[2 * NGROUPS + g];
        float4 c3 = g_prm[3 * NGROUPS + g];
        float4 c4 = g_prm[4 * NGROUPS + g];
        float4 c5 = g_prm[5 * NGROUPS + g];
        const float* pc0 = (const float*)&c0; const float* pc1 = (const float*)&c1;
        const float* pc2 = (const float*)&c2; const float* pc3 = (const float*)&c3;
        const float* pc4 = (const float*)&c4; const float* pc5 = (const float*)&c5;

        float res[12];
#pragma unroll
        for (int j = 0; j < 4; j++) {
            // row r = 4g+1+j: atoms r..r+3 start at local float 3*(1+j)
            float bond, ang, dihe;
            ic_row(a + 3 * (1 + j), bond, ang, dihe);
            res[3*j]   = fmaf(bond, pc0[j], pc1[j]);
            res[3*j+1] = fmaf(ang,  pc2[j], pc3[j]);
            float dd = dihe - pc4[j];
            dd = (dd < -PI_F) ? dd + TWO_PI : dd;
            dd = (dd >  PI_F) ? dd - TWO_PI : dd;
            res[3*j+2] = dd * pc5[j];
        }

        // results = floats 12g+12..12g+23 -> f4 indices 3g+3..3g+5 (aligned)
        outv[3*g + 3] = make_float4(res[0], res[1], res[2],  res[3]);
        outv[3*g + 4] = make_float4(res[4], res[5], res[6],  res[7]);
        outv[3*g + 5] = make_float4(res[8], res[9], res[10], res[11]);
    }

    // Row 0 + head (floats 0..11): one light thread, 3 aligned STG.128.
    if (tid == TPB - 1) {
        float bond, ang, dihe;
        ic_row(A, bond, ang, dihe);
        float ob = (bond - __ldg(mb)) * rcp_ap(__ldg(sb));
        float oa = (ang  - __ldg(ma)) * rcp_ap(__ldg(sa));
        float dd = dihe - __ldg(md);
        dd = (dd < -PI_F) ? dd + TWO_PI : dd;
        dd = (dd >  PI_F) ? dd - TWO_PI : dd;
        float od = dd * rcp_ap(__ldg(sd));
        outv[0] = make_float4(A[0], A[1], A[2], A[3]);
        outv[1] = make_float4(A[4], A[5], A[6], A[7]);
        outv[2] = make_float4(A[8], ob, oa, od);
    }
}

extern "C" void kernel_launch(void* const* d_in, const int* in_sizes, int n_in,
                              void* d_out, int out_size)
{
    const float* x  = (const float*)d_in[0];
    const float* mb = (const float*)d_in[2];
    const float* sb = (const float*)d_in[3];
    const float* ma = (const float*)d_in[4];
    const float* sa = (const float*)d_in[5];
    const float* md = (const float*)d_in[6];
    const float* sd = (const float*)d_in[7];

    int bsz = in_sizes[0] / NDIM;   // 2048

    prep_kernel<<<(NGROUPS + 255) / 256, 256>>>(mb, sb, ma, sa, md, sd);
    ict_kernel<<<bsz, TPB>>>(x, mb, sb, ma, sa, md, sd, (float*)d_out);
}

// round 12
// speedup vs baseline: 1.5902x; 1.5902x over previous
#include <cuda_runtime.h>
#include <cuda_bf16.h>

// InternalCoordinateTransform — flat, smem-free.
// z_mat row r = (r+3, r+2, r+1, r): row r reads atoms r..r+3 (floats
// 3r..3r+11), writes floats 3r+9..3r+11.
// One THREAD per (batch, group-of-4-rows): rows 4g+1..4g+4 read floats
// 12g..12g+23 (6 aligned LDG.128) and write floats 12g+12..12g+23
// (3 aligned STG.128). Params pre-packed group-SoA (prep kernel).
// R11 lesson: the 30KB-smem one-row-per-block design wave-quantizes
// (2048/(148*CTAs) waves) and caps occupancy; flat grid streams ~13 smooth
// waves with no sync and higher occupancy. Neighbor-thread read overlap
// (50%) is absorbed by L1/L2; DRAM traffic unchanged.

#define NDIM    7500
#define NF4     1875
#define NGROUPS 624           // rows 1..2496; row 0 handled by g==0 thread
#define PI_F    3.14159265358979f
#define TWO_PI  6.28318530717959f

__device__ float4 g_prm[6 * NGROUPS];  // {isb},{-mb*isb},{isa},{-ma*isa},{md},{isd}

__device__ __forceinline__ float rsqrt_ap(float x) {
    float r; asm("rsqrt.approx.f32 %0, %1;" : "=f"(r) : "f"(x)); return r;
}
__device__ __forceinline__ float sqrt_ap(float x) {
    float r; asm("sqrt.approx.f32 %0, %1;" : "=f"(r) : "f"(x)); return r;
}
__device__ __forceinline__ float rcp_ap(float x) {
    float r; asm("rcp.approx.f32 %0, %1;" : "=f"(r) : "f"(x)); return r;
}

// Hastings-style acos, |err| ~1e-7 rad, x in [-1,1].
__device__ __forceinline__ float acos_fast(float x) {
    float xa = fabsf(x);
    float p = -0.0012624911f;
    p = fmaf(p, xa,  0.0066700901f);
    p = fmaf(p, xa, -0.0170881256f);
    p = fmaf(p, xa,  0.0308918810f);
    p = fmaf(p, xa, -0.0501743046f);
    p = fmaf(p, xa,  0.0889789874f);
    p = fmaf(p, xa, -0.2145988016f);
    p = fmaf(p, xa,  1.5707963050f);
    float r = sqrt_ap(1.0f - xa) * p;
    return (x >= 0.0f) ? r : (PI_F - r);
}

// Full-quadrant atan2, |err| ~ few e-6 rad.
__device__ __forceinline__ float atan2_fast(float y, float x) {
    float ax = fabsf(x), ay = fabsf(y);
    float mx = fmaxf(fmaxf(ax, ay), 1e-35f);
    float mn = fminf(ax, ay);
    float t  = mn * rcp_ap(mx);
    float s  = t * t;
    float p = -0.01172120f;
    p = fmaf(p, s,  0.05265332f);
    p = fmaf(p, s, -0.11643287f);
    p = fmaf(p, s,  0.19354346f);
    p = fmaf(p, s, -0.33262347f);
    p = fmaf(p, s,  0.99997726f);
    float r = t * p;
    if (ay > ax)   r = 1.57079632679f - r;
    if (x < 0.0f)  r = PI_F - r;
    return copysignf(r, y);
}

// One z-row from 12 consecutive floats:
// p3=a[0..2], p2=a[3..5], p1=a[6..8], p4=a[9..11]
__device__ __forceinline__ void ic_row(const float* a, float& bond, float& ang, float& dihe)
{
    float d21x = a[3]-a[6], d21y = a[4]-a[7], d21z = a[5]-a[8];
    float d41x = a[9]-a[6], d41y = a[10]-a[7], d41z = a[11]-a[8];
    float s21 = fmaf(d21x,d21x, fmaf(d21y,d21y, d21z*d21z));
    float s41 = fmaf(d41x,d41x, fmaf(d41y,d41y, d41z*d41z));
    float r21 = rsqrt_ap(s21), r41 = rsqrt_ap(s41);
    bond = s41 * r41;
    float dotc = fmaf(d21x,d41x, fmaf(d21y,d41y, d21z*d41z));
    float cosang = fminf(fmaxf(dotc*r21*r41, -1.0f), 1.0f);
    ang = acos_fast(cosang);
    float ux = d21x*r21, uy = d21y*r21, uz = d21z*r21;
    float b0x = a[0]-a[3], b0y = a[1]-a[4], b0z = a[2]-a[5];
    float db0 = fmaf(b0x,ux, fmaf(b0y,uy, b0z*uz));
    float vx = fmaf(-db0,ux,b0x), vy = fmaf(-db0,uy,b0y), vz = fmaf(-db0,uz,b0z);
    float db2 = fmaf(d41x,ux, fmaf(d41y,uy, d41z*uz));
    float wx = fmaf(-db2,ux,d41x), wy = fmaf(-db2,uy,d41y), wz = fmaf(-db2,uz,d41z);
    float xx = fmaf(vx,wx, fmaf(vy,wy, vz*wz));
    float cx = fmaf(uy,vz,-uz*vy), cy = fmaf(uz,vx,-ux*vz), cz = fmaf(ux,vy,-uy*vx);
    float yy = fmaf(cx,wx, fmaf(cy,wy, cz*wz));
    dihe = atan2_fast(yy, xx);
}

__global__ void prep_kernel(const float* __restrict__ mb, const float* __restrict__ sb,
                            const float* __restrict__ ma, const float* __restrict__ sa,
                            const float* __restrict__ md, const float* __restrict__ sd)
{
    int g = blockIdx.x * blockDim.x + threadIdx.x;
    if (g >= NGROUPS) return;
    float4 v0, v1, v2, v3, v4, v5;
    float* p0 = (float*)&v0; float* p1 = (float*)&v1; float* p2 = (float*)&v2;
    float* p3 = (float*)&v3; float* p4 = (float*)&v4; float* p5 = (float*)&v5;
#pragma unroll
    for (int j = 0; j < 4; j++) {
        int r = 4 * g + 1 + j;
        float isb = rcp_ap(sb[r]);
        float isa = rcp_ap(sa[r]);
        float isd = rcp_ap(sd[r]);
        p0[j] = isb;   p1[j] = -mb[r] * isb;
        p2[j] = isa;   p3[j] = -ma[r] * isa;
        p4[j] = md[r]; p5[j] = isd;
    }
    g_prm[0 * NGROUPS + g] = v0;
    g_prm[1 * NGROUPS + g] = v1;
    g_prm[2 * NGROUPS + g] = v2;
    g_prm[3 * NGROUPS + g] = v3;
    g_prm[4 * NGROUPS + g] = v4;
    g_prm[5 * NGROUPS + g] = v5;
}

__global__ __launch_bounds__(128)
void ict_flat(const float* __restrict__ x,
              const float* __restrict__ mb, const float* __restrict__ sb,
              const float* __restrict__ ma, const float* __restrict__ sa,
              const float* __restrict__ md, const float* __restrict__ sd,
              float* __restrict__ out, int total)
{
    unsigned t = blockIdx.x * 128u + threadIdx.x;
    if (t >= (unsigned)total) return;
    unsigned b = t / NGROUPS;          // constant-divisor -> mulhi
    unsigned g = t - b * NGROUPS;
    const size_t base = (size_t)b * NDIM;

    const float4* __restrict__ xin  = (const float4*)(x + base);
    float4* __restrict__ outv = (float4*)(out + base);

    // ---- atoms 4g..4g+7 = floats 12g..12g+23: 6 aligned LDG.128 ----
    float a[24];
#pragma unroll
    for (int q = 0; q < 6; q++) {
        float4 f = __ldg(xin + 3 * g + q);
        a[4*q] = f.x; a[4*q+1] = f.y; a[4*q+2] = f.z; a[4*q+3] = f.w;
    }

    // ---- packed params (6 aligned LDG.128, L1/L2-resident) ----
    float4 c0 = g_prm[0 * NGROUPS + g];
    float4 c1 = g_prm[1 * NGROUPS + g];
    float4 c2 = g_prm[2 * NGROUPS + g];
    float4 c3 = g_prm[3 * NGROUPS + g];
    float4 c4 = g_prm[4 * NGROUPS + g];
    float4 c5 = g_prm[5 * NGROUPS + g];
    const float* pc0 = (const float*)&c0; const float* pc1 = (const float*)&c1;
    const float* pc2 = (const float*)&c2; const float* pc3 = (const float*)&c3;
    const float* pc4 = (const float*)&c4; const float* pc5 = (const float*)&c5;

    float res[12];
#pragma unroll
    for (int j = 0; j < 4; j++) {
        // row r = 4g+1+j: atoms r..r+3 start at local float 3*(1+j)
        float bond, ang, dihe;
        ic_row(a + 3 * (1 + j), bond, ang, dihe);
        res[3*j]   = fmaf(bond, pc0[j], pc1[j]);
        res[3*j+1] = fmaf(ang,  pc2[j], pc3[j]);
        float dd = dihe - pc4[j];
        dd = (dd < -PI_F) ? dd + TWO_PI : dd;
        dd = (dd >  PI_F) ? dd - TWO_PI : dd;
        res[3*j+2] = dd * pc5[j];
    }

    outv[3*g + 3] = make_float4(res[0], res[1], res[2],  res[3]);
    outv[3*g + 4] = make_float4(res[4], res[5], res[6],  res[7]);
    outv[3*g + 5] = make_float4(res[8], res[9], res[10], res[11]);

    // g==0 thread also handles row 0 + head floats 0..8 (all in registers).
    if (g == 0) {
        float bond, ang, dihe;
        ic_row(a, bond, ang, dihe);   // atoms 0..3 = a[0..11]
        float ob = (bond - __ldg(mb)) * rcp_ap(__ldg(sb));
        float oa = (ang  - __ldg(ma)) * rcp_ap(__ldg(sa));
        float dd = dihe - __ldg(md);
        dd = (dd < -PI_F) ? dd + TWO_PI : dd;
        dd = (dd >  PI_F) ? dd - TWO_PI : dd;
        float od = dd * rcp_ap(__ldg(sd));
        outv[0] = make_float4(a[0], a[1], a[2], a[3]);
        outv[1] = make_float4(a[4], a[5], a[6], a[7]);
        outv[2] = make_float4(a[8], ob, oa, od);
    }
}

extern "C" void kernel_launch(void* const* d_in, const int* in_sizes, int n_in,
                              void* d_out, int out_size)
{
    const float* x  = (const float*)d_in[0];
    const float* mb = (const float*)d_in[2];
    const float* sb = (const float*)d_in[3];
    const float* ma = (const float*)d_in[4];
    const float* sa = (const float*)d_in[5];
    const float* md = (const float*)d_in[6];
    const float* sd = (const float*)d_in[7];

    int bsz   = in_sizes[0] / NDIM;     // 2048
    int total = bsz * NGROUPS;          // 1,277,952 threads

    prep_kernel<<<(NGROUPS + 255) / 256, 256>>>(mb, sb, ma, sa, md, sd);
    ict_flat<<<(total + 127) / 128, 128>>>(x, mb, sb, ma, sa, md, sd,
                                           (float*)d_out, total);
}